// round 1
// baseline (speedup 1.0000x reference)
#include <cuda_runtime.h>
#include <cuda_bf16.h>
#include <math.h>

// Problem constants
#define B_  2
#define S_  2048
#define HID 2048
#define NH  16
#define HD  128
#define HALF 64
#define ROWS (B_ * S_)            // 4096
#define QKV_W (3 * HID)           // 6144
#define EPS 1e-5f
#define SCALE 0.08838834764831845f   // 1/sqrt(128)

// Scratch (device-global; no runtime allocation allowed)
__device__ float g_qkv[(size_t)ROWS * QKV_W];   // [4096, 6144] q|k|v
__device__ float g_attn[(size_t)ROWS * HID];    // [4096, 2048]
__device__ float g_cos[S_ * HALF];
__device__ float g_sin[S_ * HALF];

// ---------------------------------------------------------------------------
// RoPE table: cos/sin(pos * base^{-j/64}) for pos in [0,2048), j in [0,64)
// ---------------------------------------------------------------------------
__global__ void rope_table_kernel() {
    int idx = blockIdx.x * blockDim.x + threadIdx.x;   // 131072 entries
    if (idx >= S_ * HALF) return;
    int s = idx >> 6;
    int j = idx & 63;
    float freq = powf(10000.0f, -(float)j * (1.0f / 64.0f));
    float ang = (float)s * freq;
    float sn, cs;
    sincosf(ang, &sn, &cs);
    g_cos[idx] = cs;
    g_sin[idx] = sn;
}

// ---------------------------------------------------------------------------
// NT SGEMM: C[M,N] = A[M,K] * B[N,K]^T   (both row-major, K contiguous)
// 128x128 block tile, TK=8, 256 threads, 8x8 register micro-tile.
// M % 128 == 0, N % 128 == 0, K % 8 == 0.
// ---------------------------------------------------------------------------
__global__ void __launch_bounds__(256) gemm_nt_128(
    const float* __restrict__ A, const float* __restrict__ B,
    float* __restrict__ C, int M, int N, int K)
{
    __shared__ float As[8][128];
    __shared__ float Bs[8][128];

    const int tid = threadIdx.x;
    const int m0 = blockIdx.y * 128;
    const int n0 = blockIdx.x * 128;
    const int tx = tid & 15;
    const int ty = tid >> 4;

    const int lrow = tid >> 1;          // 0..127
    const int lcol = (tid & 1) * 4;     // 0 or 4
    const float* Ag = A + (size_t)(m0 + lrow) * K + lcol;
    const float* Bg = B + (size_t)(n0 + lrow) * K + lcol;

    float acc[8][8];
#pragma unroll
    for (int i = 0; i < 8; i++)
#pragma unroll
        for (int j = 0; j < 8; j++) acc[i][j] = 0.0f;

    for (int k0 = 0; k0 < K; k0 += 8) {
        float4 av = *(const float4*)(Ag + k0);
        float4 bv = *(const float4*)(Bg + k0);
        __syncthreads();
        As[lcol + 0][lrow] = av.x; As[lcol + 1][lrow] = av.y;
        As[lcol + 2][lrow] = av.z; As[lcol + 3][lrow] = av.w;
        Bs[lcol + 0][lrow] = bv.x; Bs[lcol + 1][lrow] = bv.y;
        Bs[lcol + 2][lrow] = bv.z; Bs[lcol + 3][lrow] = bv.w;
        __syncthreads();
#pragma unroll
        for (int kk = 0; kk < 8; kk++) {
            float a[8], b[8];
#pragma unroll
            for (int i = 0; i < 8; i++) a[i] = As[kk][ty * 8 + i];
#pragma unroll
            for (int j = 0; j < 8; j++) b[j] = Bs[kk][tx * 8 + j];
#pragma unroll
            for (int i = 0; i < 8; i++)
#pragma unroll
                for (int j = 0; j < 8; j++)
                    acc[i][j] = fmaf(a[i], b[j], acc[i][j]);
        }
    }

#pragma unroll
    for (int i = 0; i < 8; i++) {
        float* Cp = C + (size_t)(m0 + ty * 8 + i) * N + n0 + tx * 8;
        ((float4*)Cp)[0] = make_float4(acc[i][0], acc[i][1], acc[i][2], acc[i][3]);
        ((float4*)Cp)[1] = make_float4(acc[i][4], acc[i][5], acc[i][6], acc[i][7]);
    }
}

// ---------------------------------------------------------------------------
// Fused qk RMSNorm (flat 2048) + RoPE (rotate-half, per head of 128).
// One block per (b,s) row; q then k.
// ---------------------------------------------------------------------------
__global__ void __launch_bounds__(256) normrope_kernel(
    float* __restrict__ qkv,
    const float* __restrict__ nw_q, const float* __restrict__ nw_k)
{
    __shared__ float buf[HID];
    __shared__ float warpred[8];

    const int row = blockIdx.x;      // 0..4095
    const int s = row & (S_ - 1);
    float* base = qkv + (size_t)row * QKV_W;
    const int tid = threadIdx.x;

#pragma unroll
    for (int part = 0; part < 2; part++) {
        float* src = base + part * HID;
        const float* w = (part == 0) ? nw_q : nw_k;

        float ss = 0.0f;
#pragma unroll
        for (int u = 0; u < 8; u++) {
            int idx = tid + u * 256;
            float v = src[idx];
            buf[idx] = v;
            ss += v * v;
        }
#pragma unroll
        for (int o = 16; o; o >>= 1) ss += __shfl_xor_sync(0xffffffffu, ss, o);
        if ((tid & 31) == 0) warpred[tid >> 5] = ss;
        __syncthreads();
        float tot = 0.0f;
#pragma unroll
        for (int wi = 0; wi < 8; wi++) tot += warpred[wi];
        float rn = rsqrtf(tot * (1.0f / (float)HID) + EPS);

        // RoPE: 1024 (j, j+64) pairs
#pragma unroll
        for (int u = 0; u < 4; u++) {
            int p = tid + u * 256;
            int hh = p >> 6;
            int j = p & 63;
            int i1 = hh * HD + j;
            int i2 = i1 + HALF;
            float x1 = buf[i1] * rn * w[i1];
            float x2 = buf[i2] * rn * w[i2];
            float cs = g_cos[s * HALF + j];
            float sn = g_sin[s * HALF + j];
            src[i1] = x1 * cs - x2 * sn;
            src[i2] = x2 * cs + x1 * sn;
        }
        __syncthreads();   // buf/warpred reuse in next part
    }
}

// ---------------------------------------------------------------------------
// Causal flash attention, fp32 SIMT.
// grid: (32 q-tiles [reversed for load balance], 32 = B*NH). 256 threads.
// Tiles 64x64, HD=128. Dynamic smem: Q(32K) + KV(32K) + S(16K) = 80KB.
// ---------------------------------------------------------------------------
__global__ void __launch_bounds__(256) attn_kernel(
    const float* __restrict__ qkv, float* __restrict__ out)
{
    extern __shared__ float sm[];
    float* Qs = sm;                    // [64][128]
    float* KVs = Qs + 64 * HD;         // [64][128]
    float* Ss = KVs + 64 * HD;         // [64][64]
    __shared__ float m_s[64], l_s[64], alpha_s[64];

    const int tid = threadIdx.x;
    const int bh = blockIdx.y;
    const int b = bh / NH;
    const int h = bh % NH;
    const int qt = gridDim.x - 1 - blockIdx.x;   // heavy tiles first
    const int q0 = qt * 64;
    const int nkb = qt + 1;

    const int tx = tid & 15;
    const int ty = tid >> 4;
    const int i0 = ty * 4;      // 4 rows
    const int j0 = tx * 4;      // 4 score cols
    const int c0 = tx * 8;      // 8 output cols

    const size_t rowbase = (size_t)(b * S_) * QKV_W + (size_t)h * HD;

    // Load Q tile
#pragma unroll
    for (int u = 0; u < 8; u++) {
        int idx = tid + u * 256;       // 0..2047 float4s
        int r = idx >> 5;
        int c4 = (idx & 31) * 4;
        float4 v = *(const float4*)(qkv + rowbase + (size_t)(q0 + r) * QKV_W + c4);
        *(float4*)&Qs[r * HD + c4] = v;
    }

    if (tid < 64) { m_s[tid] = -1e30f; l_s[tid] = 0.0f; }

    float acc_o[4][8];
#pragma unroll
    for (int i = 0; i < 4; i++)
#pragma unroll
        for (int c = 0; c < 8; c++) acc_o[i][c] = 0.0f;

    for (int kb = 0; kb < nkb; kb++) {
        const int k0s = kb * 64;
        // K tile -> regs
        float4 kreg[8];
#pragma unroll
        for (int u = 0; u < 8; u++) {
            int idx = tid + u * 256;
            int r = idx >> 5;
            int c4 = (idx & 31) * 4;
            kreg[u] = *(const float4*)(qkv + rowbase + (size_t)(k0s + r) * QKV_W + HID + c4);
        }
        __syncthreads();   // prev PV done with KVs/Ss (also orders m/l init)
#pragma unroll
        for (int u = 0; u < 8; u++) {
            int idx = tid + u * 256;
            int r = idx >> 5;
            int c4 = (idx & 31) * 4;
            *(float4*)&KVs[r * HD + c4] = kreg[u];
        }
        __syncthreads();

        // scores: 4x4 micro-tile per thread
        float accs[4][4];
#pragma unroll
        for (int i = 0; i < 4; i++)
#pragma unroll
            for (int j = 0; j < 4; j++) accs[i][j] = 0.0f;
        for (int d = 0; d < HD; d += 4) {
            float4 qv[4], kv[4];
#pragma unroll
            for (int i = 0; i < 4; i++) qv[i] = *(const float4*)&Qs[(i0 + i) * HD + d];
#pragma unroll
            for (int j = 0; j < 4; j++) kv[j] = *(const float4*)&KVs[(j0 + j) * HD + d];
#pragma unroll
            for (int i = 0; i < 4; i++)
#pragma unroll
                for (int j = 0; j < 4; j++) {
                    accs[i][j] = fmaf(qv[i].x, kv[j].x, accs[i][j]);
                    accs[i][j] = fmaf(qv[i].y, kv[j].y, accs[i][j]);
                    accs[i][j] = fmaf(qv[i].z, kv[j].z, accs[i][j]);
                    accs[i][j] = fmaf(qv[i].w, kv[j].w, accs[i][j]);
                }
        }
#pragma unroll
        for (int i = 0; i < 4; i++)
#pragma unroll
            for (int j = 0; j < 4; j++) {
                float v = accs[i][j] * SCALE;
                if (k0s + j0 + j > q0 + i0 + i) v = -1e30f;
                Ss[(i0 + i) * 64 + j0 + j] = v;
            }

        // V tile -> regs (overlap with softmax pass)
        float4 vreg[8];
#pragma unroll
        for (int u = 0; u < 8; u++) {
            int idx = tid + u * 256;
            int r = idx >> 5;
            int c4 = (idx & 31) * 4;
            vreg[u] = *(const float4*)(qkv + rowbase + (size_t)(k0s + r) * QKV_W + 2 * HID + c4);
        }
        __syncthreads();

        // online softmax row pass (64 threads)
        if (tid < 64) {
            float mo = m_s[tid];
            float mx = mo;
            float* srow = &Ss[tid * 64];
#pragma unroll 8
            for (int j = 0; j < 64; j++) mx = fmaxf(mx, srow[j]);
            float alpha = __expf(mo - mx);
            float lsum = 0.0f;
#pragma unroll 8
            for (int j = 0; j < 64; j++) {
                float p = __expf(srow[j] - mx);
                srow[j] = p;
                lsum += p;
            }
            l_s[tid] = l_s[tid] * alpha + lsum;
            m_s[tid] = mx;
            alpha_s[tid] = alpha;
        }
        __syncthreads();

        // store V tile (K reads done)
#pragma unroll
        for (int u = 0; u < 8; u++) {
            int idx = tid + u * 256;
            int r = idx >> 5;
            int c4 = (idx & 31) * 4;
            *(float4*)&KVs[r * HD + c4] = vreg[u];
        }
        __syncthreads();

        // O = O*alpha + P @ V
#pragma unroll
        for (int i = 0; i < 4; i++) {
            float al = alpha_s[i0 + i];
#pragma unroll
            for (int c = 0; c < 8; c++) acc_o[i][c] *= al;
        }
        for (int j = 0; j < 64; j++) {
            float p[4];
#pragma unroll
            for (int i = 0; i < 4; i++) p[i] = Ss[(i0 + i) * 64 + j];
            float4 v0 = *(const float4*)&KVs[j * HD + c0];
            float4 v1 = *(const float4*)&KVs[j * HD + c0 + 4];
#pragma unroll
            for (int i = 0; i < 4; i++) {
                acc_o[i][0] = fmaf(p[i], v0.x, acc_o[i][0]);
                acc_o[i][1] = fmaf(p[i], v0.y, acc_o[i][1]);
                acc_o[i][2] = fmaf(p[i], v0.z, acc_o[i][2]);
                acc_o[i][3] = fmaf(p[i], v0.w, acc_o[i][3]);
                acc_o[i][4] = fmaf(p[i], v1.x, acc_o[i][4]);
                acc_o[i][5] = fmaf(p[i], v1.y, acc_o[i][5]);
                acc_o[i][6] = fmaf(p[i], v1.z, acc_o[i][6]);
                acc_o[i][7] = fmaf(p[i], v1.w, acc_o[i][7]);
            }
        }
    }

    // write O / l to g_attn [b, s, h*128 + c]
#pragma unroll
    for (int i = 0; i < 4; i++) {
        float inv = 1.0f / l_s[i0 + i];
        float* op = out + (size_t)(b * S_ + q0 + i0 + i) * HID + h * HD + c0;
        ((float4*)op)[0] = make_float4(acc_o[i][0] * inv, acc_o[i][1] * inv,
                                       acc_o[i][2] * inv, acc_o[i][3] * inv);
        ((float4*)op)[1] = make_float4(acc_o[i][4] * inv, acc_o[i][5] * inv,
                                       acc_o[i][6] * inv, acc_o[i][7] * inv);
    }
}

// ---------------------------------------------------------------------------
// launch
// ---------------------------------------------------------------------------
extern "C" void kernel_launch(void* const* d_in, const int* in_sizes, int n_in,
                              void* d_out, int out_size)
{
    const float* x     = (const float*)d_in[0];   // [2,2048,2048]
    const float* w_in  = (const float*)d_in[1];   // [6144,2048]
    const float* w_out = (const float*)d_in[2];   // [2048,2048]
    const float* qnw   = (const float*)d_in[3];   // [2048]
    const float* knw   = (const float*)d_in[4];   // [2048]
    float* out = (float*)d_out;                   // [2,2048,2048]

    float* qkv;  cudaGetSymbolAddress((void**)&qkv,  g_qkv);
    float* attn; cudaGetSymbolAddress((void**)&attn, g_attn);

    // 1. QKV = X @ Win^T : [4096, 6144]
    gemm_nt_128<<<dim3(QKV_W / 128, ROWS / 128), 256>>>(x, w_in, qkv, ROWS, QKV_W, HID);

    // 2. RoPE tables + fused qk-RMSNorm/RoPE (in place)
    rope_table_kernel<<<(S_ * HALF + 255) / 256, 256>>>();
    normrope_kernel<<<ROWS, 256>>>(qkv, qnw, knw);

    // 3. causal flash attention -> g_attn [4096, 2048]
    static const int attn_smem = (64 * HD + 64 * HD + 64 * 64) * (int)sizeof(float); // 80KB
    cudaFuncSetAttribute(attn_kernel, cudaFuncAttributeMaxDynamicSharedMemorySize, attn_smem);
    attn_kernel<<<dim3(S_ / 64, B_ * NH), 256, attn_smem>>>(qkv, attn);

    // 4. out = attn @ Wout^T : [4096, 2048]
    gemm_nt_128<<<dim3(HID / 128, ROWS / 128), 256>>>(attn, w_out, out, ROWS, HID, HID);
}

// round 3
// speedup vs baseline: 1.4882x; 1.4882x over previous
#include <cuda_runtime.h>
#include <cuda_bf16.h>
#include <cstdint>
#include <math.h>

// Problem constants
#define B_  2
#define S_  2048
#define HID 2048
#define NH  16
#define HD  128
#define HALF 64
#define ROWS (B_ * S_)            // 4096
#define QKV_W (3 * HID)           // 6144
#define EPS 1e-5f
#define SCALE 0.08838834764831845f   // 1/sqrt(128)

#define K3 6144                   // extended K = 3 * 2048 (3xBF16 split)

// Scratch (device-global; no runtime allocation allowed)
__device__ float g_qkv[(size_t)ROWS * QKV_W];            // [4096, 6144]
__device__ float g_attn[(size_t)ROWS * HID];             // [4096, 2048]
__device__ float g_cos[S_ * HALF];
__device__ float g_sin[S_ * HALF];
__device__ __nv_bfloat16 g_ext_a[(size_t)ROWS * K3];     // 50 MB  (Aext)
__device__ __nv_bfloat16 g_ext_b[(size_t)QKV_W * K3];    // 75 MB  (Bext, reused)

__device__ __forceinline__ uint32_t smem_u32(const void* p) {
    uint32_t a;
    asm("{ .reg .u64 t; cvta.to.shared.u64 t, %1; cvt.u32.u64 %0, t; }" : "=r"(a) : "l"(p));
    return a;
}

#define SWZ(x) ((x) ^ (((x) >> 3) & 0x70))

// ---------------------------------------------------------------------------
// RoPE table
// ---------------------------------------------------------------------------
__global__ void rope_table_kernel() {
    int idx = blockIdx.x * blockDim.x + threadIdx.x;
    if (idx >= S_ * HALF) return;
    int s = idx >> 6;
    int j = idx & 63;
    float freq = powf(10000.0f, -(float)j * (1.0f / 64.0f));
    float sn, cs;
    sincosf((float)s * freq, &sn, &cs);
    g_cos[idx] = cs;
    g_sin[idx] = sn;
}

// ---------------------------------------------------------------------------
// 3xBF16 split: src fp32 [rows, 2048] -> dst bf16 [rows, 6144]
// aorder=1: [hi | hi | lo]   aorder=0: [hi | lo | hi]
// ---------------------------------------------------------------------------
__global__ void __launch_bounds__(256) split3_kernel(
    const float* __restrict__ src, __nv_bfloat16* __restrict__ dst,
    int n4, int aorder)
{
    int i = blockIdx.x * blockDim.x + threadIdx.x;
    if (i >= n4) return;
    float4 v = ((const float4*)src)[i];
    int idx = i * 4;
    int r = idx >> 11;
    int k = idx & 2047;
    float vv[4] = {v.x, v.y, v.z, v.w};
    uint64_t hp = 0, lp = 0;
#pragma unroll
    for (int q = 0; q < 4; q++) {
        __nv_bfloat16 h = __float2bfloat16(vv[q]);
        __nv_bfloat16 l = __float2bfloat16(vv[q] - __bfloat162float(h));
        hp |= (uint64_t)__bfloat16_as_ushort(h) << (q * 16);
        lp |= (uint64_t)__bfloat16_as_ushort(l) << (q * 16);
    }
    __nv_bfloat16* rowp = dst + (size_t)r * K3 + k;
    *(uint64_t*)(rowp)        = hp;
    *(uint64_t*)(rowp + 2048) = aorder ? hp : lp;
    *(uint64_t*)(rowp + 4096) = aorder ? lp : hp;
}

// ---------------------------------------------------------------------------
// bf16 mma.sync GEMM: C[M,N] = A[M,6144] * B[N,6144]^T  (fp32 out)
// Tile 128x256, BK=64, 3-stage cp.async, 512 threads (16 warps, 4x4 grid),
// warp tile 32x64. ldmatrix.x4 fragment loads from xor-swizzled smem.
// ---------------------------------------------------------------------------
#define BM 128
#define BN 256
#define BK 64
#define NKIT (K3 / BK)                          // 96
#define NSTAGE 3
#define A_BYTES (BM * 128)                      // 16384
#define B_BYTES (BN * 128)                      // 32768
#define STAGE_BYTES (A_BYTES + B_BYTES)         // 49152
#define GEMM_SMEM (NSTAGE * STAGE_BYTES)        // 147456

__device__ __forceinline__ void ldsm_x4(uint32_t* r, uint32_t addr) {
    asm volatile("ldmatrix.sync.aligned.m8n8.x4.shared.b16 {%0,%1,%2,%3}, [%4];"
                 : "=r"(r[0]), "=r"(r[1]), "=r"(r[2]), "=r"(r[3]) : "r"(addr));
}
__device__ __forceinline__ void mma_bf16(float* c, const uint32_t* a,
                                         uint32_t b0, uint32_t b1) {
    asm volatile(
        "mma.sync.aligned.m16n8k16.row.col.f32.bf16.bf16.f32 "
        "{%0,%1,%2,%3}, {%4,%5,%6,%7}, {%8,%9}, {%0,%1,%2,%3};"
        : "+f"(c[0]), "+f"(c[1]), "+f"(c[2]), "+f"(c[3])
        : "r"(a[0]), "r"(a[1]), "r"(a[2]), "r"(a[3]), "r"(b0), "r"(b1));
}

__global__ void __launch_bounds__(512, 1) gemm_mma(
    const __nv_bfloat16* __restrict__ A, const __nv_bfloat16* __restrict__ B,
    float* __restrict__ C, int M, int N)
{
    extern __shared__ char smem[];
    const uint32_t sb = smem_u32(smem);
    const int tid = threadIdx.x;
    const int wid = tid >> 5, lid = tid & 31;
    const int tiles_m = M / BM;
    const int m0 = (blockIdx.x % tiles_m) * BM;
    const int n0 = (blockIdx.x / tiles_m) * BN;
    const int wm = (wid & 3) * 32;       // warp m offset in tile
    const int wn = (wid >> 2) * 64;      // warp n offset in tile

    const char* Ab = (const char*)(A + (size_t)m0 * K3);
    const char* Bb = (const char*)(B + (size_t)n0 * K3);

    // per-thread load slots: 6 chunks of 16B (A: 1024 chunks, B: 2048)
    int ld_r[6], ld_c[6];       // row, 16B-col
    uint32_t ld_soff[6];        // swizzled smem offset within stage
    bool ld_isA[6];
#pragma unroll
    for (int u = 0; u < 6; u++) {
        int c = tid + u * 512;
        if (c < 1024) {
            int r = c >> 3, c16 = c & 7;
            ld_isA[u] = true; ld_r[u] = r; ld_c[u] = c16;
            ld_soff[u] = SWZ(r * 128 + c16 * 16);
        } else {
            int cc = c - 1024;
            int r = cc >> 3, c16 = cc & 7;
            ld_isA[u] = false; ld_r[u] = r; ld_c[u] = c16;
            ld_soff[u] = A_BYTES + SWZ(r * 128 + c16 * 16);
        }
    }

#define LOAD_STAGE(s, kt) do {                                                 \
    uint32_t sbase = sb + (s) * STAGE_BYTES;                                   \
    _Pragma("unroll")                                                          \
    for (int u = 0; u < 6; u++) {                                              \
        const char* src = (ld_isA[u] ? Ab : Bb) +                              \
            ((size_t)ld_r[u] * K3 + (kt) * BK) * 2 + ld_c[u] * 16;             \
        asm volatile("cp.async.cg.shared.global [%0], [%1], 16;"               \
                     :: "r"(sbase + ld_soff[u]), "l"(src) : "memory");         \
    }                                                                          \
} while (0)

    // prologue: stages 0..NSTAGE-2
#pragma unroll
    for (int s = 0; s < NSTAGE - 1; s++) {
        LOAD_STAGE(s, s);
        asm volatile("cp.async.commit_group;" ::: "memory");
    }

    float acc[2][8][4];
#pragma unroll
    for (int mt = 0; mt < 2; mt++)
#pragma unroll
        for (int nt = 0; nt < 8; nt++)
#pragma unroll
            for (int q = 0; q < 4; q++) acc[mt][nt][q] = 0.0f;

    // precomputed ldmatrix lane geometry
    const int lrow = lid & 15;           // row within 16-row group
    const int lhi = (lid >> 4) * 16;     // 0 or 16 bytes (k half)

    for (int kt = 0; kt < NKIT; kt++) {
        if (kt + NSTAGE - 1 < NKIT) LOAD_STAGE((kt + NSTAGE - 1) % NSTAGE, kt + NSTAGE - 1);
        asm volatile("cp.async.commit_group;" ::: "memory");
        asm volatile("cp.async.wait_group %0;" :: "n"(NSTAGE - 1) : "memory");
        __syncthreads();

        const uint32_t sA = sb + (kt % NSTAGE) * STAGE_BYTES;
        const uint32_t sB = sA + A_BYTES;

#pragma unroll
        for (int ks = 0; ks < 4; ks++) {
            const int cb = ks * 32 + lhi;
            uint32_t af[2][4];
#pragma unroll
            for (int mt = 0; mt < 2; mt++) {
                int row = wm + mt * 16 + lrow;
                ldsm_x4(af[mt], sA + row * 128 + (cb ^ ((row & 7) * 16)));
            }
            uint32_t bfg[4][4];
#pragma unroll
            for (int np = 0; np < 4; np++) {
                int row = wn + np * 16 + lrow;
                ldsm_x4(bfg[np], sB + row * 128 + (cb ^ ((row & 7) * 16)));
            }
#pragma unroll
            for (int mt = 0; mt < 2; mt++)
#pragma unroll
                for (int np = 0; np < 4; np++) {
                    mma_bf16(acc[mt][np * 2 + 0], af[mt], bfg[np][0], bfg[np][2]);
                    mma_bf16(acc[mt][np * 2 + 1], af[mt], bfg[np][1], bfg[np][3]);
                }
        }
        __syncthreads();
    }

    // epilogue: c0,c1 -> (row, col..col+1), c2,c3 -> (row+8, ...)
    const int erow = m0 + wm + (lid >> 2);
    const int ecol = n0 + wn + (lid & 3) * 2;
#pragma unroll
    for (int mt = 0; mt < 2; mt++)
#pragma unroll
        for (int nt = 0; nt < 8; nt++) {
            float* c0 = C + (size_t)(erow + mt * 16) * N + ecol + nt * 8;
            *(float2*)c0 = make_float2(acc[mt][nt][0], acc[mt][nt][1]);
            float* c1 = c0 + 8 * N;
            *(float2*)c1 = make_float2(acc[mt][nt][2], acc[mt][nt][3]);
        }
#undef LOAD_STAGE
}

// ---------------------------------------------------------------------------
// Fused qk RMSNorm (flat 2048) + RoPE (rotate-half). One block per row.
// ---------------------------------------------------------------------------
__global__ void __launch_bounds__(256) normrope_kernel(
    float* __restrict__ qkv,
    const float* __restrict__ nw_q, const float* __restrict__ nw_k)
{
    __shared__ float buf[HID];
    __shared__ float warpred[8];

    const int row = blockIdx.x;
    const int s = row & (S_ - 1);
    float* base = qkv + (size_t)row * QKV_W;
    const int tid = threadIdx.x;

#pragma unroll
    for (int part = 0; part < 2; part++) {
        float* src = base + part * HID;
        const float* w = (part == 0) ? nw_q : nw_k;

        float ss = 0.0f;
#pragma unroll
        for (int u = 0; u < 8; u++) {
            int idx = tid + u * 256;
            float v = src[idx];
            buf[idx] = v;
            ss += v * v;
        }
#pragma unroll
        for (int o = 16; o; o >>= 1) ss += __shfl_xor_sync(0xffffffffu, ss, o);
        if ((tid & 31) == 0) warpred[tid >> 5] = ss;
        __syncthreads();
        float tot = 0.0f;
#pragma unroll
        for (int wi = 0; wi < 8; wi++) tot += warpred[wi];
        float rn = rsqrtf(tot * (1.0f / (float)HID) + EPS);

#pragma unroll
        for (int u = 0; u < 4; u++) {
            int p = tid + u * 256;
            int hh = p >> 6;
            int j = p & 63;
            int i1 = hh * HD + j;
            int i2 = i1 + HALF;
            float x1 = buf[i1] * rn * w[i1];
            float x2 = buf[i2] * rn * w[i2];
            float cs = g_cos[s * HALF + j];
            float sn = g_sin[s * HALF + j];
            src[i1] = x1 * cs - x2 * sn;
            src[i2] = x2 * cs + x1 * sn;
        }
        __syncthreads();
    }
}

// ---------------------------------------------------------------------------
// Causal flash attention, fp32 SIMT (unchanged from R1).
// ---------------------------------------------------------------------------
__global__ void __launch_bounds__(256) attn_kernel(
    const float* __restrict__ qkv, float* __restrict__ out)
{
    extern __shared__ float sm[];
    float* Qs = sm;
    float* KVs = Qs + 64 * HD;
    float* Ss = KVs + 64 * HD;
    __shared__ float m_s[64], l_s[64], alpha_s[64];

    const int tid = threadIdx.x;
    const int bh = blockIdx.y;
    const int b = bh / NH;
    const int h = bh % NH;
    const int qt = gridDim.x - 1 - blockIdx.x;
    const int q0 = qt * 64;
    const int nkb = qt + 1;

    const int tx = tid & 15;
    const int ty = tid >> 4;
    const int i0 = ty * 4;
    const int j0 = tx * 4;
    const int c0 = tx * 8;

    const size_t rowbase = (size_t)(b * S_) * QKV_W + (size_t)h * HD;

#pragma unroll
    for (int u = 0; u < 8; u++) {
        int idx = tid + u * 256;
        int r = idx >> 5;
        int c4 = (idx & 31) * 4;
        float4 v = *(const float4*)(qkv + rowbase + (size_t)(q0 + r) * QKV_W + c4);
        *(float4*)&Qs[r * HD + c4] = v;
    }

    if (tid < 64) { m_s[tid] = -1e30f; l_s[tid] = 0.0f; }

    float acc_o[4][8];
#pragma unroll
    for (int i = 0; i < 4; i++)
#pragma unroll
        for (int c = 0; c < 8; c++) acc_o[i][c] = 0.0f;

    for (int kb = 0; kb < nkb; kb++) {
        const int k0s = kb * 64;
        float4 kreg[8];
#pragma unroll
        for (int u = 0; u < 8; u++) {
            int idx = tid + u * 256;
            int r = idx >> 5;
            int c4 = (idx & 31) * 4;
            kreg[u] = *(const float4*)(qkv + rowbase + (size_t)(k0s + r) * QKV_W + HID + c4);
        }
        __syncthreads();
#pragma unroll
        for (int u = 0; u < 8; u++) {
            int idx = tid + u * 256;
            int r = idx >> 5;
            int c4 = (idx & 31) * 4;
            *(float4*)&KVs[r * HD + c4] = kreg[u];
        }
        __syncthreads();

        float accs[4][4];
#pragma unroll
        for (int i = 0; i < 4; i++)
#pragma unroll
            for (int j = 0; j < 4; j++) accs[i][j] = 0.0f;
        for (int d = 0; d < HD; d += 4) {
            float4 qv[4], kv[4];
#pragma unroll
            for (int i = 0; i < 4; i++) qv[i] = *(const float4*)&Qs[(i0 + i) * HD + d];
#pragma unroll
            for (int j = 0; j < 4; j++) kv[j] = *(const float4*)&KVs[(j0 + j) * HD + d];
#pragma unroll
            for (int i = 0; i < 4; i++)
#pragma unroll
                for (int j = 0; j < 4; j++) {
                    accs[i][j] = fmaf(qv[i].x, kv[j].x, accs[i][j]);
                    accs[i][j] = fmaf(qv[i].y, kv[j].y, accs[i][j]);
                    accs[i][j] = fmaf(qv[i].z, kv[j].z, accs[i][j]);
                    accs[i][j] = fmaf(qv[i].w, kv[j].w, accs[i][j]);
                }
        }
#pragma unroll
        for (int i = 0; i < 4; i++)
#pragma unroll
            for (int j = 0; j < 4; j++) {
                float v = accs[i][j] * SCALE;
                if (k0s + j0 + j > q0 + i0 + i) v = -1e30f;
                Ss[(i0 + i) * 64 + j0 + j] = v;
            }

        float4 vreg[8];
#pragma unroll
        for (int u = 0; u < 8; u++) {
            int idx = tid + u * 256;
            int r = idx >> 5;
            int c4 = (idx & 31) * 4;
            vreg[u] = *(const float4*)(qkv + rowbase + (size_t)(k0s + r) * QKV_W + 2 * HID + c4);
        }
        __syncthreads();

        if (tid < 64) {
            float mo = m_s[tid];
            float mx = mo;
            float* srow = &Ss[tid * 64];
#pragma unroll 8
            for (int j = 0; j < 64; j++) mx = fmaxf(mx, srow[j]);
            float alpha = __expf(mo - mx);
            float lsum = 0.0f;
#pragma unroll 8
            for (int j = 0; j < 64; j++) {
                float p = __expf(srow[j] - mx);
                srow[j] = p;
                lsum += p;
            }
            l_s[tid] = l_s[tid] * alpha + lsum;
            m_s[tid] = mx;
            alpha_s[tid] = alpha;
        }
        __syncthreads();

#pragma unroll
        for (int u = 0; u < 8; u++) {
            int idx = tid + u * 256;
            int r = idx >> 5;
            int c4 = (idx & 31) * 4;
            *(float4*)&KVs[r * HD + c4] = vreg[u];
        }
        __syncthreads();

#pragma unroll
        for (int i = 0; i < 4; i++) {
            float al = alpha_s[i0 + i];
#pragma unroll
            for (int c = 0; c < 8; c++) acc_o[i][c] *= al;
        }
        for (int j = 0; j < 64; j++) {
            float p[4];
#pragma unroll
            for (int i = 0; i < 4; i++) p[i] = Ss[(i0 + i) * 64 + j];
            float4 v0 = *(const float4*)&KVs[j * HD + c0];
            float4 v1 = *(const float4*)&KVs[j * HD + c0 + 4];
#pragma unroll
            for (int i = 0; i < 4; i++) {
                acc_o[i][0] = fmaf(p[i], v0.x, acc_o[i][0]);
                acc_o[i][1] = fmaf(p[i], v0.y, acc_o[i][1]);
                acc_o[i][2] = fmaf(p[i], v0.z, acc_o[i][2]);
                acc_o[i][3] = fmaf(p[i], v0.w, acc_o[i][3]);
                acc_o[i][4] = fmaf(p[i], v1.x, acc_o[i][4]);
                acc_o[i][5] = fmaf(p[i], v1.y, acc_o[i][5]);
                acc_o[i][6] = fmaf(p[i], v1.z, acc_o[i][6]);
                acc_o[i][7] = fmaf(p[i], v1.w, acc_o[i][7]);
            }
        }
    }

#pragma unroll
    for (int i = 0; i < 4; i++) {
        float inv = 1.0f / l_s[i0 + i];
        float* op = out + (size_t)(b * S_ + q0 + i0 + i) * HID + h * HD + c0;
        ((float4*)op)[0] = make_float4(acc_o[i][0] * inv, acc_o[i][1] * inv,
                                       acc_o[i][2] * inv, acc_o[i][3] * inv);
        ((float4*)op)[1] = make_float4(acc_o[i][4] * inv, acc_o[i][5] * inv,
                                       acc_o[i][6] * inv, acc_o[i][7] * inv);
    }
}

// ---------------------------------------------------------------------------
// launch
// ---------------------------------------------------------------------------
extern "C" void kernel_launch(void* const* d_in, const int* in_sizes, int n_in,
                              void* d_out, int out_size)
{
    const float* x     = (const float*)d_in[0];
    const float* w_in  = (const float*)d_in[1];
    const float* w_out = (const float*)d_in[2];
    const float* qnw   = (const float*)d_in[3];
    const float* knw   = (const float*)d_in[4];
    float* out = (float*)d_out;

    float* qkv;  cudaGetSymbolAddress((void**)&qkv,  g_qkv);
    float* attn; cudaGetSymbolAddress((void**)&attn, g_attn);
    __nv_bfloat16* ea; cudaGetSymbolAddress((void**)&ea, g_ext_a);
    __nv_bfloat16* eb; cudaGetSymbolAddress((void**)&eb, g_ext_b);

    cudaFuncSetAttribute(gemm_mma, cudaFuncAttributeMaxDynamicSharedMemorySize, GEMM_SMEM);

    // 1. split x -> Aext [4096,6144], w_in -> Bext [6144,6144]
    split3_kernel<<<(ROWS * HID / 4 + 255) / 256, 256>>>(x, ea, ROWS * HID / 4, 1);
    split3_kernel<<<(QKV_W * HID / 4 + 255) / 256, 256>>>(w_in, eb, QKV_W * HID / 4, 0);

    // 2. QKV = Aext @ Bext^T  (bf16 mma.sync, 3xBF16)
    gemm_mma<<<(ROWS / BM) * (QKV_W / BN), 512, GEMM_SMEM>>>(ea, eb, qkv, ROWS, QKV_W);

    // 3. RoPE tables + fused qk-RMSNorm/RoPE (in place)
    rope_table_kernel<<<(S_ * HALF + 255) / 256, 256>>>();
    normrope_kernel<<<ROWS, 256>>>(qkv, qnw, knw);

    // 4. causal flash attention -> g_attn
    static const int attn_smem = (64 * HD + 64 * HD + 64 * 64) * (int)sizeof(float);
    cudaFuncSetAttribute(attn_kernel, cudaFuncAttributeMaxDynamicSharedMemorySize, attn_smem);
    attn_kernel<<<dim3(S_ / 64, B_ * NH), 256, attn_smem>>>(qkv, attn);

    // 5. split attn -> Aext, w_out -> Bext [2048,6144]
    split3_kernel<<<(ROWS * HID / 4 + 255) / 256, 256>>>(attn, ea, ROWS * HID / 4, 1);
    split3_kernel<<<(HID * HID / 4 + 255) / 256, 256>>>(w_out, eb, HID * HID / 4, 0);

    // 6. out = Aext @ Bext^T
    gemm_mma<<<(ROWS / BM) * (HID / BN), 512, GEMM_SMEM>>>(ea, eb, out, ROWS, HID);
}

// round 4
// speedup vs baseline: 3.8887x; 2.6130x over previous
#include <cuda_runtime.h>
#include <cuda_bf16.h>
#include <cstdint>
#include <math.h>

// Problem constants
#define B_  2
#define S_  2048
#define HID 2048
#define NH  16
#define HD  128
#define HALF 64
#define ROWS (B_ * S_)            // 4096
#define QKV_W (3 * HID)           // 6144
#define EPS 1e-5f
#define SCALE 0.08838834764831845f   // 1/sqrt(128)

#define K3 6144                   // extended K = 3 * 2048 (3xBF16 split)

// Scratch (device-global; no runtime allocation allowed)
__device__ float g_qkv[(size_t)ROWS * QKV_W];            // 100 MB (gemm1 out)
__device__ float g_cos[S_ * HALF];
__device__ float g_sin[S_ * HALF];
__device__ __nv_bfloat16 g_ext_a[(size_t)ROWS * K3];     // 50 MB  gemm A-ext (x; then O)
__device__ __nv_bfloat16 g_ext_b[(size_t)QKV_W * K3];    // 75 MB  gemm B-ext (w_in; then w_out)
__device__ __nv_bfloat16 g_q_hi[(size_t)ROWS * HID];     // 16 MB each
__device__ __nv_bfloat16 g_q_lo[(size_t)ROWS * HID];
__device__ __nv_bfloat16 g_k_hi[(size_t)ROWS * HID];
__device__ __nv_bfloat16 g_k_lo[(size_t)ROWS * HID];
__device__ __nv_bfloat16 g_vt_hi[(size_t)ROWS * HID];    // [b][h][d][s]
__device__ __nv_bfloat16 g_vt_lo[(size_t)ROWS * HID];

__device__ __forceinline__ uint32_t smem_u32(const void* p) {
    uint32_t a;
    asm("{ .reg .u64 t; cvta.to.shared.u64 t, %1; cvt.u32.u64 %0, t; }" : "=r"(a) : "l"(p));
    return a;
}
#define SWZ(x) ((x) ^ (((x) >> 3) & 0x70))

__device__ __forceinline__ void ldsm_x4(uint32_t* r, uint32_t addr) {
    asm volatile("ldmatrix.sync.aligned.m8n8.x4.shared.b16 {%0,%1,%2,%3}, [%4];"
                 : "=r"(r[0]), "=r"(r[1]), "=r"(r[2]), "=r"(r[3]) : "r"(addr));
}
__device__ __forceinline__ void mma_bf16(float* c, const uint32_t* a,
                                         uint32_t b0, uint32_t b1) {
    asm volatile(
        "mma.sync.aligned.m16n8k16.row.col.f32.bf16.bf16.f32 "
        "{%0,%1,%2,%3}, {%4,%5,%6,%7}, {%8,%9}, {%0,%1,%2,%3};"
        : "+f"(c[0]), "+f"(c[1]), "+f"(c[2]), "+f"(c[3])
        : "r"(a[0]), "r"(a[1]), "r"(a[2]), "r"(a[3]), "r"(b0), "r"(b1));
}
__device__ __forceinline__ uint32_t pack_bf16x2(float lo, float hi) {
    uint32_t r;
    asm("cvt.rn.bf16x2.f32 %0, %1, %2;" : "=r"(r) : "f"(hi), "f"(lo));
    return r;
}

// ---------------------------------------------------------------------------
// RoPE table
// ---------------------------------------------------------------------------
__global__ void rope_table_kernel() {
    int idx = blockIdx.x * blockDim.x + threadIdx.x;
    if (idx >= S_ * HALF) return;
    int s = idx >> 6;
    int j = idx & 63;
    float freq = powf(10000.0f, -(float)j * (1.0f / 64.0f));
    float sn, cs;
    sincosf((float)s * freq, &sn, &cs);
    g_cos[idx] = cs;
    g_sin[idx] = sn;
}

// ---------------------------------------------------------------------------
// 3xBF16 split: src fp32 [rows, 2048] -> dst bf16 [rows, 6144]
// aorder=1: [hi | hi | lo]   aorder=0: [hi | lo | hi]
// ---------------------------------------------------------------------------
__global__ void __launch_bounds__(256) split3_kernel(
    const float* __restrict__ src, __nv_bfloat16* __restrict__ dst,
    int n4, int aorder)
{
    int i = blockIdx.x * blockDim.x + threadIdx.x;
    if (i >= n4) return;
    float4 v = ((const float4*)src)[i];
    int idx = i * 4;
    int r = idx >> 11;
    int k = idx & 2047;
    float vv[4] = {v.x, v.y, v.z, v.w};
    uint64_t hp = 0, lp = 0;
#pragma unroll
    for (int q = 0; q < 4; q++) {
        __nv_bfloat16 h = __float2bfloat16(vv[q]);
        __nv_bfloat16 l = __float2bfloat16(vv[q] - __bfloat162float(h));
        hp |= (uint64_t)__bfloat16_as_ushort(h) << (q * 16);
        lp |= (uint64_t)__bfloat16_as_ushort(l) << (q * 16);
    }
    __nv_bfloat16* rowp = dst + (size_t)r * K3 + k;
    *(uint64_t*)(rowp)        = hp;
    *(uint64_t*)(rowp + 2048) = aorder ? hp : lp;
    *(uint64_t*)(rowp + 4096) = aorder ? lp : hp;
}

// ---------------------------------------------------------------------------
// bf16 mma.sync GEMM (validated R3): C[M,N] = A[M,6144]*B[N,6144]^T
// ---------------------------------------------------------------------------
#define BM 128
#define BN 256
#define BK 64
#define NKIT (K3 / BK)
#define NSTAGE 3
#define A_BYTES (BM * 128)
#define B_BYTES (BN * 128)
#define STAGE_BYTES (A_BYTES + B_BYTES)
#define GEMM_SMEM (NSTAGE * STAGE_BYTES)

__global__ void __launch_bounds__(512, 1) gemm_mma(
    const __nv_bfloat16* __restrict__ A, const __nv_bfloat16* __restrict__ B,
    float* __restrict__ C, int M, int N)
{
    extern __shared__ char smem[];
    const uint32_t sb = smem_u32(smem);
    const int tid = threadIdx.x;
    const int wid = tid >> 5, lid = tid & 31;
    const int tiles_m = M / BM;
    const int m0 = (blockIdx.x % tiles_m) * BM;
    const int n0 = (blockIdx.x / tiles_m) * BN;
    const int wm = (wid & 3) * 32;
    const int wn = (wid >> 2) * 64;

    const char* Ab = (const char*)(A + (size_t)m0 * K3);
    const char* Bb = (const char*)(B + (size_t)n0 * K3);

    int ld_r[6], ld_c[6];
    uint32_t ld_soff[6];
    bool ld_isA[6];
#pragma unroll
    for (int u = 0; u < 6; u++) {
        int c = tid + u * 512;
        if (c < 1024) {
            int r = c >> 3, c16 = c & 7;
            ld_isA[u] = true; ld_r[u] = r; ld_c[u] = c16;
            ld_soff[u] = SWZ(r * 128 + c16 * 16);
        } else {
            int cc = c - 1024;
            int r = cc >> 3, c16 = cc & 7;
            ld_isA[u] = false; ld_r[u] = r; ld_c[u] = c16;
            ld_soff[u] = A_BYTES + SWZ(r * 128 + c16 * 16);
        }
    }

#define LOAD_STAGE(s, kt) do {                                                 \
    uint32_t sbase = sb + (s) * STAGE_BYTES;                                   \
    _Pragma("unroll")                                                          \
    for (int u = 0; u < 6; u++) {                                              \
        const char* src = (ld_isA[u] ? Ab : Bb) +                              \
            ((size_t)ld_r[u] * K3 + (kt) * BK) * 2 + ld_c[u] * 16;             \
        asm volatile("cp.async.cg.shared.global [%0], [%1], 16;"               \
                     :: "r"(sbase + ld_soff[u]), "l"(src) : "memory");         \
    }                                                                          \
} while (0)

#pragma unroll
    for (int s = 0; s < NSTAGE - 1; s++) {
        LOAD_STAGE(s, s);
        asm volatile("cp.async.commit_group;" ::: "memory");
    }

    float acc[2][8][4];
#pragma unroll
    for (int mt = 0; mt < 2; mt++)
#pragma unroll
        for (int nt = 0; nt < 8; nt++)
#pragma unroll
            for (int q = 0; q < 4; q++) acc[mt][nt][q] = 0.0f;

    const int lrow = lid & 15;
    const int lhi = (lid >> 4) * 16;

    for (int kt = 0; kt < NKIT; kt++) {
        if (kt + NSTAGE - 1 < NKIT) LOAD_STAGE((kt + NSTAGE - 1) % NSTAGE, kt + NSTAGE - 1);
        asm volatile("cp.async.commit_group;" ::: "memory");
        asm volatile("cp.async.wait_group %0;" :: "n"(NSTAGE - 1) : "memory");
        __syncthreads();

        const uint32_t sA = sb + (kt % NSTAGE) * STAGE_BYTES;
        const uint32_t sB = sA + A_BYTES;

#pragma unroll
        for (int ks = 0; ks < 4; ks++) {
            const int cb = ks * 32 + lhi;
            uint32_t af[2][4];
#pragma unroll
            for (int mt = 0; mt < 2; mt++) {
                int row = wm + mt * 16 + lrow;
                ldsm_x4(af[mt], sA + row * 128 + (cb ^ ((row & 7) * 16)));
            }
            uint32_t bfg[4][4];
#pragma unroll
            for (int np = 0; np < 4; np++) {
                int row = wn + np * 16 + lrow;
                ldsm_x4(bfg[np], sB + row * 128 + (cb ^ ((row & 7) * 16)));
            }
#pragma unroll
            for (int mt = 0; mt < 2; mt++)
#pragma unroll
                for (int np = 0; np < 4; np++) {
                    mma_bf16(acc[mt][np * 2 + 0], af[mt], bfg[np][0], bfg[np][2]);
                    mma_bf16(acc[mt][np * 2 + 1], af[mt], bfg[np][1], bfg[np][3]);
                }
        }
        __syncthreads();
    }

    const int erow = m0 + wm + (lid >> 2);
    const int ecol = n0 + wn + (lid & 3) * 2;
#pragma unroll
    for (int mt = 0; mt < 2; mt++)
#pragma unroll
        for (int nt = 0; nt < 8; nt++) {
            float* c0 = C + (size_t)(erow + mt * 16) * N + ecol + nt * 8;
            *(float2*)c0 = make_float2(acc[mt][nt][0], acc[mt][nt][1]);
            float* c1 = c0 + 8 * N;
            *(float2*)c1 = make_float2(acc[mt][nt][2], acc[mt][nt][3]);
        }
#undef LOAD_STAGE
}

// ---------------------------------------------------------------------------
// Fused qk RMSNorm + RoPE -> bf16 hi/lo planes. Q scaled by 1/sqrt(HD).
// ---------------------------------------------------------------------------
__global__ void __launch_bounds__(256) normrope_kernel(
    const float* __restrict__ qkv,
    const float* __restrict__ nw_q, const float* __restrict__ nw_k,
    __nv_bfloat16* __restrict__ qh, __nv_bfloat16* __restrict__ ql,
    __nv_bfloat16* __restrict__ kh, __nv_bfloat16* __restrict__ kl)
{
    __shared__ float buf[HID];
    __shared__ float warpred[8];

    const int row = blockIdx.x;
    const int s = row & (S_ - 1);
    const int tid = threadIdx.x;

#pragma unroll
    for (int part = 0; part < 2; part++) {
        const float* src = qkv + (size_t)row * QKV_W + part * HID;
        const float* w = (part == 0) ? nw_q : nw_k;
        __nv_bfloat16* dh = (part == 0) ? qh : kh;
        __nv_bfloat16* dl = (part == 0) ? ql : kl;

        float ss = 0.0f;
#pragma unroll
        for (int u = 0; u < 8; u++) {
            int idx = tid + u * 256;
            float v = src[idx];
            buf[idx] = v;
            ss += v * v;
        }
#pragma unroll
        for (int o = 16; o; o >>= 1) ss += __shfl_xor_sync(0xffffffffu, ss, o);
        if ((tid & 31) == 0) warpred[tid >> 5] = ss;
        __syncthreads();
        float tot = 0.0f;
#pragma unroll
        for (int wi = 0; wi < 8; wi++) tot += warpred[wi];
        float rn = rsqrtf(tot * (1.0f / (float)HID) + EPS);
        if (part == 0) rn *= SCALE;

#pragma unroll
        for (int u = 0; u < 4; u++) {
            int p = tid + u * 256;
            int hh = p >> 6;
            int j = p & 63;
            int i1 = hh * HD + j;
            int i2 = i1 + HALF;
            float x1 = buf[i1] * rn * w[i1];
            float x2 = buf[i2] * rn * w[i2];
            float cs = g_cos[s * HALF + j];
            float sn = g_sin[s * HALF + j];
            float o1 = x1 * cs - x2 * sn;
            float o2 = x2 * cs + x1 * sn;
            __nv_bfloat16 h1 = __float2bfloat16(o1);
            __nv_bfloat16 h2 = __float2bfloat16(o2);
            size_t base = (size_t)row * HID;
            dh[base + i1] = h1;
            dh[base + i2] = h2;
            dl[base + i1] = __float2bfloat16(o1 - __bfloat162float(h1));
            dl[base + i2] = __float2bfloat16(o2 - __bfloat162float(h2));
        }
        __syncthreads();
    }
}

// ---------------------------------------------------------------------------
// V transpose + split: g_qkv v cols -> vt_hi/vt_lo [b][h][d][s]
// ---------------------------------------------------------------------------
__global__ void __launch_bounds__(256) vtrans_kernel(
    const float* __restrict__ qkv,
    __nv_bfloat16* __restrict__ vth, __nv_bfloat16* __restrict__ vtl)
{
    __shared__ float t[32][33];
    const int row0 = blockIdx.x * 32;         // (b,s) rows
    const int col0 = blockIdx.y * 32;         // (h,d) cols within 2048
    const int tx = threadIdx.x & 31;
    const int ty = threadIdx.x >> 5;          // 0..7
#pragma unroll
    for (int i = 0; i < 4; i++) {
        int r = ty + i * 8;
        t[r][tx] = qkv[(size_t)(row0 + r) * QKV_W + 2 * HID + col0 + tx];
    }
    __syncthreads();
    const int b = row0 >> 11;
    const int s0 = row0 & 2047;
#pragma unroll
    for (int i = 0; i < 4; i++) {
        int c = ty + i * 8;
        float v = t[tx][c];
        __nv_bfloat16 h = __float2bfloat16(v);
        size_t o = ((size_t)(b * 2048 + col0 + c)) * 2048 + s0 + tx;
        vth[o] = h;
        vtl[o] = __float2bfloat16(v - __bfloat162float(h));
    }
}

// ---------------------------------------------------------------------------
// Flash attention via bf16 mma.sync with 3-term hi/lo split.
// Block: 128 q rows x one (b,h). 8 warps (16 rows each). 2-stage KV pipeline.
// Output written directly as gemm2 A-ext [hi|hi|lo] into g_ext_a.
// ---------------------------------------------------------------------------
#define SQH 0
#define SQL 32768
#define SKH(s) (65536 + (s) * 65536)
#define SKL(s) (SKH(s) + 16384)
#define SVH(s) (SKH(s) + 32768)
#define SVL(s) (SKH(s) + 49152)
#define ATTN_SMEM (65536 + 2 * 65536)   // 196608

__global__ void __launch_bounds__(256, 1) attn_mma(
    const __nv_bfloat16* __restrict__ qh, const __nv_bfloat16* __restrict__ ql,
    const __nv_bfloat16* __restrict__ kh, const __nv_bfloat16* __restrict__ kl,
    const __nv_bfloat16* __restrict__ vth, const __nv_bfloat16* __restrict__ vtl,
    __nv_bfloat16* __restrict__ oext)
{
    extern __shared__ char smem[];
    const uint32_t sb = smem_u32(smem);
    const int tid = threadIdx.x;
    const int wid = tid >> 5, lid = tid & 31;
    const int lrow = lid & 15;
    const int lhi = (lid >> 4) * 16;
    const int bh = blockIdx.y;
    const int b = bh >> 4, h = bh & 15;
    const int qt = gridDim.x - 1 - blockIdx.x;
    const int q0 = qt * 128;
    const int nkb = qt * 2 + 2;
    const int wm = wid * 16;

    // ---- load Q (hi+lo) into smem ----
#pragma unroll
    for (int u = 0; u < 16; u++) {
        int c = tid + u * 256;               // 0..4095
        int plane = c >> 11;
        int cc = c & 2047;
        int r = cc >> 4, ch = cc & 15;
        int p = ch >> 3, c8 = ch & 7;
        const __nv_bfloat16* src = (plane ? ql : qh) +
            ((size_t)(b * 2048 + q0 + r) * HID + h * HD + ch * 8);
        uint32_t dst = sb + (plane ? SQL : SQH) + p * 16384 + SWZ(r * 128 + c8 * 16);
        asm volatile("cp.async.cg.shared.global [%0], [%1], 16;"
                     :: "r"(dst), "l"(src) : "memory");
    }
    asm volatile("cp.async.commit_group;" ::: "memory");

#define LOAD_KV(s, kt) do {                                                    \
    int k0 = (kt) * 64;                                                        \
    _Pragma("unroll")                                                          \
    for (int u = 0; u < 16; u++) {                                             \
        int c = tid + u * 256;                                                 \
        if (c < 2048) {                                                        \
            int plane = c >> 10;                                               \
            int cc = c & 1023;                                                 \
            int r = cc >> 4, ch = cc & 15;                                     \
            int p = ch >> 3, c8 = ch & 7;                                      \
            const __nv_bfloat16* src = (plane ? kl : kh) +                     \
                ((size_t)(b * 2048 + k0 + r) * HID + h * HD + ch * 8);         \
            uint32_t dst = sb + (plane ? SKL(s) : SKH(s)) + p * 8192 +         \
                           SWZ(r * 128 + c8 * 16);                             \
            asm volatile("cp.async.cg.shared.global [%0], [%1], 16;"           \
                         :: "r"(dst), "l"(src) : "memory");                    \
        } else {                                                               \
            int plane = (c >> 10) & 1;                                         \
            int cc = c & 1023;                                                 \
            int d = cc >> 3, c8 = cc & 7;                                      \
            const __nv_bfloat16* src = (plane ? vtl : vth) +                   \
                ((size_t)(b * 2048 + h * HD + d) * 2048 + k0 + c8 * 8);        \
            uint32_t dst = sb + (plane ? SVL(s) : SVH(s)) +                    \
                           SWZ(d * 128 + c8 * 16);                             \
            asm volatile("cp.async.cg.shared.global [%0], [%1], 16;"           \
                         :: "r"(dst), "l"(src) : "memory");                    \
        }                                                                      \
    }                                                                          \
} while (0)

    LOAD_KV(0, 0);
    asm volatile("cp.async.commit_group;" ::: "memory");

    float accO[16][4];
#pragma unroll
    for (int nt = 0; nt < 16; nt++)
#pragma unroll
        for (int q = 0; q < 4; q++) accO[nt][q] = 0.0f;
    float m0v = -1e30f, m1v = -1e30f, l0v = 0.0f, l1v = 0.0f;

    const int grow0 = q0 + wm + (lid >> 2);
    const int grow1 = grow0 + 8;

    for (int kt = 0; kt < nkb; kt++) {
        __syncthreads();     // protect stage reuse
        if (kt + 1 < nkb) LOAD_KV((kt + 1) & 1, kt + 1);
        asm volatile("cp.async.commit_group;" ::: "memory");
        asm volatile("cp.async.wait_group 1;" ::: "memory");
        __syncthreads();

        const int s = kt & 1;

        // ---- S = Qh*Kh + Ql*Kh + Qh*Kl ----
        float sa[8][4];
#pragma unroll
        for (int nt = 0; nt < 8; nt++)
#pragma unroll
            for (int q = 0; q < 4; q++) sa[nt][q] = 0.0f;

#pragma unroll
        for (int t = 0; t < 3; t++) {
            const uint32_t qbase = sb + (t == 1 ? SQL : SQH);
            const uint32_t kbase = sb + (t == 2 ? SKL(s) : SKH(s));
#pragma unroll
            for (int kk = 0; kk < 8; kk++) {
                int p = kk >> 2;
                int cb = (kk & 3) * 32 + lhi;
                int arow = wm + lrow;
                uint32_t af[4];
                ldsm_x4(af, qbase + p * 16384 + arow * 128 + (cb ^ ((arow & 7) * 16)));
#pragma unroll
                for (int np = 0; np < 4; np++) {
                    int brow = np * 16 + lrow;
                    uint32_t bf4[4];
                    ldsm_x4(bf4, kbase + p * 8192 + brow * 128 + (cb ^ ((brow & 7) * 16)));
                    mma_bf16(sa[np * 2 + 0], af, bf4[0], bf4[2]);
                    mma_bf16(sa[np * 2 + 1], af, bf4[1], bf4[3]);
                }
            }
        }

        // ---- causal mask ----
        if ((kt + 1) * 64 - 1 > q0 + wm) {
            const int colb = kt * 64 + (lid & 3) * 2;
#pragma unroll
            for (int nt = 0; nt < 8; nt++) {
                int col = colb + nt * 8;
                if (col > grow0)     sa[nt][0] = -1e30f;
                if (col + 1 > grow0) sa[nt][1] = -1e30f;
                if (col > grow1)     sa[nt][2] = -1e30f;
                if (col + 1 > grow1) sa[nt][3] = -1e30f;
            }
        }

        // ---- online softmax (rows grow0, grow1) ----
        float mx0 = m0v, mx1 = m1v;
#pragma unroll
        for (int nt = 0; nt < 8; nt++) {
            mx0 = fmaxf(mx0, fmaxf(sa[nt][0], sa[nt][1]));
            mx1 = fmaxf(mx1, fmaxf(sa[nt][2], sa[nt][3]));
        }
        mx0 = fmaxf(mx0, __shfl_xor_sync(0xffffffffu, mx0, 1));
        mx0 = fmaxf(mx0, __shfl_xor_sync(0xffffffffu, mx0, 2));
        mx1 = fmaxf(mx1, __shfl_xor_sync(0xffffffffu, mx1, 1));
        mx1 = fmaxf(mx1, __shfl_xor_sync(0xffffffffu, mx1, 2));
        float alpha0 = __expf(m0v - mx0);
        float alpha1 = __expf(m1v - mx1);
        m0v = mx0; m1v = mx1;

        float ls0 = 0.0f, ls1 = 0.0f;
#pragma unroll
        for (int nt = 0; nt < 8; nt++) {
            sa[nt][0] = __expf(sa[nt][0] - mx0);
            sa[nt][1] = __expf(sa[nt][1] - mx0);
            sa[nt][2] = __expf(sa[nt][2] - mx1);
            sa[nt][3] = __expf(sa[nt][3] - mx1);
            ls0 += sa[nt][0] + sa[nt][1];
            ls1 += sa[nt][2] + sa[nt][3];
        }
        ls0 += __shfl_xor_sync(0xffffffffu, ls0, 1);
        ls0 += __shfl_xor_sync(0xffffffffu, ls0, 2);
        ls1 += __shfl_xor_sync(0xffffffffu, ls1, 1);
        ls1 += __shfl_xor_sync(0xffffffffu, ls1, 2);
        l0v = l0v * alpha0 + ls0;
        l1v = l1v * alpha1 + ls1;

#pragma unroll
        for (int nt = 0; nt < 16; nt++) {
            accO[nt][0] *= alpha0; accO[nt][1] *= alpha0;
            accO[nt][2] *= alpha1; accO[nt][3] *= alpha1;
        }

        // ---- P split into bf16 hi/lo A-fragments ----
        uint32_t phA[8], phB[8], plA[8], plB[8];
#pragma unroll
        for (int nt = 0; nt < 8; nt++) {
            float h0 = __bfloat162float(__float2bfloat16(sa[nt][0]));
            float h1 = __bfloat162float(__float2bfloat16(sa[nt][1]));
            float h2 = __bfloat162float(__float2bfloat16(sa[nt][2]));
            float h3 = __bfloat162float(__float2bfloat16(sa[nt][3]));
            phA[nt] = pack_bf16x2(h0, h1);
            phB[nt] = pack_bf16x2(h2, h3);
            plA[nt] = pack_bf16x2(sa[nt][0] - h0, sa[nt][1] - h1);
            plB[nt] = pack_bf16x2(sa[nt][2] - h2, sa[nt][3] - h3);
        }

        // ---- O += Ph*Vh + Pl*Vh + Ph*Vl ----
#pragma unroll
        for (int t = 0; t < 3; t++) {
            const uint32_t vbase = sb + (t == 2 ? SVL(s) : SVH(s));
            const uint32_t* pa = (t == 1) ? plA : phA;
            const uint32_t* pb = (t == 1) ? plB : phB;
#pragma unroll
            for (int ki = 0; ki < 4; ki++) {
                uint32_t a[4] = {pa[2 * ki], pb[2 * ki], pa[2 * ki + 1], pb[2 * ki + 1]};
                int cb = ki * 32 + lhi;
#pragma unroll
                for (int np = 0; np < 8; np++) {
                    int brow = np * 16 + lrow;
                    uint32_t bf4[4];
                    ldsm_x4(bf4, vbase + brow * 128 + (cb ^ ((brow & 7) * 16)));
                    mma_bf16(accO[np * 2 + 0], a, bf4[0], bf4[2]);
                    mma_bf16(accO[np * 2 + 1], a, bf4[1], bf4[3]);
                }
            }
        }
    }

    // ---- epilogue: O/l -> oext [hi|hi|lo] ----
    float inv0 = 1.0f / l0v, inv1 = 1.0f / l1v;
#pragma unroll
    for (int nt = 0; nt < 16; nt++) {
        int col = h * HD + nt * 8 + (lid & 3) * 2;
        float o0 = accO[nt][0] * inv0, o1 = accO[nt][1] * inv0;
        float o2 = accO[nt][2] * inv1, o3 = accO[nt][3] * inv1;
        float h0 = __bfloat162float(__float2bfloat16(o0));
        float h1 = __bfloat162float(__float2bfloat16(o1));
        float h2 = __bfloat162float(__float2bfloat16(o2));
        float h3 = __bfloat162float(__float2bfloat16(o3));
        uint32_t hi0 = pack_bf16x2(h0, h1);
        uint32_t hi1 = pack_bf16x2(h2, h3);
        uint32_t lo0 = pack_bf16x2(o0 - h0, o1 - h1);
        uint32_t lo1 = pack_bf16x2(o2 - h2, o3 - h3);
        __nv_bfloat16* r0 = oext + (size_t)(b * 2048 + grow0) * K3 + col;
        __nv_bfloat16* r1 = oext + (size_t)(b * 2048 + grow1) * K3 + col;
        *(uint32_t*)(r0) = hi0; *(uint32_t*)(r0 + 2048) = hi0; *(uint32_t*)(r0 + 4096) = lo0;
        *(uint32_t*)(r1) = hi1; *(uint32_t*)(r1 + 2048) = hi1; *(uint32_t*)(r1 + 4096) = lo1;
    }
#undef LOAD_KV
}

// ---------------------------------------------------------------------------
// launch
// ---------------------------------------------------------------------------
extern "C" void kernel_launch(void* const* d_in, const int* in_sizes, int n_in,
                              void* d_out, int out_size)
{
    const float* x     = (const float*)d_in[0];
    const float* w_in  = (const float*)d_in[1];
    const float* w_out = (const float*)d_in[2];
    const float* qnw   = (const float*)d_in[3];
    const float* knw   = (const float*)d_in[4];
    float* out = (float*)d_out;

    float* qkv;  cudaGetSymbolAddress((void**)&qkv,  g_qkv);
    __nv_bfloat16 *ea, *eb, *qh, *ql, *kh, *kl, *vth, *vtl;
    cudaGetSymbolAddress((void**)&ea, g_ext_a);
    cudaGetSymbolAddress((void**)&eb, g_ext_b);
    cudaGetSymbolAddress((void**)&qh, g_q_hi);
    cudaGetSymbolAddress((void**)&ql, g_q_lo);
    cudaGetSymbolAddress((void**)&kh, g_k_hi);
    cudaGetSymbolAddress((void**)&kl, g_k_lo);
    cudaGetSymbolAddress((void**)&vth, g_vt_hi);
    cudaGetSymbolAddress((void**)&vtl, g_vt_lo);

    cudaFuncSetAttribute(gemm_mma, cudaFuncAttributeMaxDynamicSharedMemorySize, GEMM_SMEM);
    cudaFuncSetAttribute(attn_mma, cudaFuncAttributeMaxDynamicSharedMemorySize, ATTN_SMEM);

    // 1. split x -> ea, w_in -> eb
    split3_kernel<<<(ROWS * HID / 4 + 255) / 256, 256>>>(x, ea, ROWS * HID / 4, 1);
    split3_kernel<<<(QKV_W * HID / 4 + 255) / 256, 256>>>(w_in, eb, QKV_W * HID / 4, 0);

    // 2. QKV = x @ w_in^T
    gemm_mma<<<(ROWS / BM) * (QKV_W / BN), 512, GEMM_SMEM>>>(ea, eb, qkv, ROWS, QKV_W);

    // 3. tables + norm/rope -> bf16 planes; V transpose/split
    rope_table_kernel<<<(S_ * HALF + 255) / 256, 256>>>();
    normrope_kernel<<<ROWS, 256>>>(qkv, qnw, knw, qh, ql, kh, kl);
    vtrans_kernel<<<dim3(ROWS / 32, HID / 32), 256>>>(qkv, vth, vtl);

    // 4. attention -> ea (gemm2 A-ext layout)
    attn_mma<<<dim3(S_ / 128, B_ * NH), 256, ATTN_SMEM>>>(qh, ql, kh, kl, vth, vtl, ea);

    // 5. w_out -> eb; out = O @ w_out^T
    split3_kernel<<<(HID * HID / 4 + 255) / 256, 256>>>(w_out, eb, HID * HID / 4, 0);
    gemm_mma<<<(ROWS / BM) * (HID / BN), 512, GEMM_SMEM>>>(ea, eb, out, ROWS, HID);
}